// round 1
// baseline (speedup 1.0000x reference)
#include <cuda_runtime.h>
#include <math.h>

#define N_NODES 50000
#define N_EDGES 800000
#define FC      128
#define FE      64
#define HID     384
#define DOUT    128
#define TM      64      // edges per CTA
#define HSTR    385     // padded row stride for s_h (conflict-free column walks)

// Scratch (static __device__ allowed; no cudaMalloc anywhere)
__device__ float g_P[(size_t)N_NODES * HID];     // vc@W1[0:128]
__device__ float g_Q[(size_t)N_NODES * HID];     // vc@W1[128:256] + b1
__device__ float g_W23[HID * DOUT];              // W2[:,1:] @ W3
__device__ float g_w20[HID];                     // W2[:,0]
__device__ float g_c0[DOUT];                     // b2[1:] @ W3
__device__ float g_b20;                          // b2[0]

// ---------------- Precompute W23 = W2[:,1:] @ W3  (384 x 128) ----------------
__global__ void k_w23(const float* __restrict__ W2, const float* __restrict__ W3) {
    __shared__ float s[512];
    int k = blockIdx.x;          // 0..383
    int t = threadIdx.x;         // 0..127
    for (int j = t; j < 512; j += 128) s[j] = W2[k * 513 + 1 + j];
    __syncthreads();
    float acc = 0.f;
#pragma unroll 8
    for (int j = 0; j < 512; j++) acc = fmaf(s[j], W3[j * DOUT + t], acc);
    g_W23[k * DOUT + t] = acc;
}

// ---------------- Small constants: w20, c0, b20 ----------------
__global__ void k_misc(const float* __restrict__ W2, const float* __restrict__ b2,
                       const float* __restrict__ W3) {
    int t = threadIdx.x;  // 512 threads
    if (t < HID) g_w20[t] = W2[t * 513];
    if (t < DOUT) {
        float acc = 0.f;
        for (int j = 0; j < 512; j++) acc = fmaf(b2[1 + j], W3[j * DOUT + t], acc);
        g_c0[t] = acc;
    }
    if (t == 0) g_b20 = b2[0];
}

// ---------------- P/Q node precompute: 16 nodes per block ----------------
// grid (3125, 2), block 128.  part=0 -> P (W1 rows 0:128), part=1 -> Q (+b1)
__global__ void __launch_bounds__(128) k_pq(const float* __restrict__ vc,
                                            const float* __restrict__ W1,
                                            const float* __restrict__ b1) {
    __shared__ float sv[16 * FC];
    int part = blockIdx.y;
    int n0   = blockIdx.x * 16;
    int t    = threadIdx.x;
    for (int idx = t; idx < 16 * FC; idx += 128) sv[idx] = vc[(size_t)n0 * FC + idx];
    __syncthreads();

    float acc[16][3];
#pragma unroll
    for (int i = 0; i < 16; i++) { acc[i][0] = 0.f; acc[i][1] = 0.f; acc[i][2] = 0.f; }

    const float* Wb = W1 + (size_t)part * FC * HID;
#pragma unroll 2
    for (int k = 0; k < FC; k++) {
        float w0 = Wb[k * HID + t];
        float w1 = Wb[k * HID + t + 128];
        float w2 = Wb[k * HID + t + 256];
#pragma unroll
        for (int i = 0; i < 16; i++) {
            float v = sv[i * FC + k];
            acc[i][0] = fmaf(v, w0, acc[i][0]);
            acc[i][1] = fmaf(v, w1, acc[i][1]);
            acc[i][2] = fmaf(v, w2, acc[i][2]);
        }
    }
    float* dstp = part ? g_Q : g_P;
    float bb0 = 0.f, bb1 = 0.f, bb2 = 0.f;
    if (part) { bb0 = b1[t]; bb1 = b1[t + 128]; bb2 = b1[t + 256]; }
#pragma unroll
    for (int i = 0; i < 16; i++) {
        size_t base = (size_t)(n0 + i) * HID;
        dstp[base + t]       = acc[i][0] + bb0;
        dstp[base + t + 128] = acc[i][1] + bb1;
        dstp[base + t + 256] = acc[i][2] + bb2;
    }
}

// ---------------- Fused edge kernel ----------------
// h  = relu(P[src] + Q[dst] + ve@W1[256:384])          (64 x 384)
// out = sigmoid(h.w20 + b20) * (h@W23 + c0) + b3       (64 x 128)
__global__ void __launch_bounds__(256) k_edge(
    const float* __restrict__ ve1, const float* __restrict__ ve2,
    const int*   __restrict__ src, const int* __restrict__ dst,
    const float* __restrict__ W1,  const float* __restrict__ b3,
    float* __restrict__ out)
{
    extern __shared__ float sm[];
    float* s_ve = sm;                   // 64 x 128
    float* s_h  = sm + TM * 128;        // 64 x 385 (padded)
    float* s_g  = s_h + TM * HSTR;      // 64

    int t  = threadIdx.x;
    int e0 = blockIdx.x * TM;

    // Load edge features: s_ve[r][k] = (k<64 ? ve1 : ve2)
    for (int idx = t; idx < TM * 128; idx += 256) {
        int r = idx >> 7, k = idx & 127;
        float v = (k < 64) ? ve1[(size_t)(e0 + r) * 64 + k]
                           : ve2[(size_t)(e0 + r) * 64 + (k - 64)];
        s_ve[idx] = v;
    }
    // Gather P[src] + Q[dst] into s_h (b1 already folded into Q)
    for (int r = 0; r < TM; r++) {
        int s = src[e0 + r], d = dst[e0 + r];
        const float* Pp = g_P + (size_t)s * HID;
        const float* Qp = g_Q + (size_t)d * HID;
        for (int c = t; c < HID; c += 256) s_h[r * HSTR + c] = Pp[c] + Qp[c];
    }
    __syncthreads();

    // ---- Stage A: h += ve @ W1[256:384], relu.  2 passes of 32 rows. ----
    int ct = t & 63, rt = t >> 6;          // 64 col-threads x 4 row-threads
    const float* Wve = W1 + 256 * HID;
#pragma unroll 1
    for (int p = 0; p < 2; p++) {
        int rbase = p * 32 + rt * 8;
        float acc[8][6];
#pragma unroll
        for (int i = 0; i < 8; i++)
#pragma unroll
            for (int j = 0; j < 6; j++) acc[i][j] = s_h[(rbase + i) * HSTR + ct + j * 64];
#pragma unroll 2
        for (int k = 0; k < 128; k++) {
            float wv[6];
#pragma unroll
            for (int j = 0; j < 6; j++) wv[j] = Wve[k * HID + ct + j * 64];
#pragma unroll
            for (int i = 0; i < 8; i++) {
                float xv = s_ve[(rbase + i) * 128 + k];
#pragma unroll
                for (int j = 0; j < 6; j++) acc[i][j] = fmaf(xv, wv[j], acc[i][j]);
            }
        }
#pragma unroll
        for (int i = 0; i < 8; i++)
#pragma unroll
            for (int j = 0; j < 6; j++)
                s_h[(rbase + i) * HSTR + ct + j * 64] = fmaxf(acc[i][j], 0.f);
    }
    __syncthreads();

    // ---- Gate: s_g[r] = sigmoid(h[r].w20 + b20) ----
    if (t < TM) {
        float acc = 0.f;
#pragma unroll 4
        for (int c = 0; c < HID; c++) acc = fmaf(s_h[t * HSTR + c], g_w20[c], acc);
        s_g[t] = 1.f / (1.f + expf(-(acc + g_b20)));
    }
    __syncthreads();

    // ---- Stage B: out = gate * (h @ W23 + c0) + b3 ----
    int lane = t & 31, warp = t >> 5;
    int rb = warp * 8;
    float4 acc[8];
#pragma unroll
    for (int i = 0; i < 8; i++) acc[i] = make_float4(0.f, 0.f, 0.f, 0.f);
    const float4* W23v = (const float4*)g_W23;
#pragma unroll 4
    for (int c = 0; c < HID; c++) {
        float4 w = W23v[c * 32 + lane];
#pragma unroll
        for (int i = 0; i < 8; i++) {
            float h = s_h[(rb + i) * HSTR + c];
            acc[i].x = fmaf(h, w.x, acc[i].x);
            acc[i].y = fmaf(h, w.y, acc[i].y);
            acc[i].z = fmaf(h, w.z, acc[i].z);
            acc[i].w = fmaf(h, w.w, acc[i].w);
        }
    }
    float4 cv = ((const float4*)g_c0)[lane];
    float4 bv = ((const float4*)b3)[lane];
#pragma unroll
    for (int i = 0; i < 8; i++) {
        float kk = s_g[rb + i];
        float4 o;
        o.x = fmaf(kk, acc[i].x + cv.x, bv.x);
        o.y = fmaf(kk, acc[i].y + cv.y, bv.y);
        o.z = fmaf(kk, acc[i].z + cv.z, bv.z);
        o.w = fmaf(kk, acc[i].w + cv.w, bv.w);
        ((float4*)out)[(size_t)(e0 + rb + i) * 32 + lane] = o;
    }
}

extern "C" void kernel_launch(void* const* d_in, const int* in_sizes, int n_in,
                              void* d_out, int out_size) {
    const float* vc  = (const float*)d_in[0];
    const float* ve1 = (const float*)d_in[1];
    const float* ve2 = (const float*)d_in[2];
    const int*   src = (const int*)  d_in[3];
    const int*   dst = (const int*)  d_in[4];
    const float* W1  = (const float*)d_in[5];
    const float* b1  = (const float*)d_in[6];
    const float* W2  = (const float*)d_in[7];
    const float* b2  = (const float*)d_in[8];
    const float* W3  = (const float*)d_in[9];
    const float* b3  = (const float*)d_in[10];
    float* out = (float*)d_out;

    const int smem_bytes = (TM * 128 + TM * HSTR + TM) * (int)sizeof(float); // 131584
    cudaFuncSetAttribute(k_edge, cudaFuncAttributeMaxDynamicSharedMemorySize, smem_bytes);

    k_w23 <<<HID, 128>>>(W2, W3);
    k_misc<<<1, 512>>>(W2, b2, W3);
    k_pq  <<<dim3(N_NODES / 16, 2), 128>>>(vc, W1, b1);
    k_edge<<<N_EDGES / TM, 256, smem_bytes>>>(ve1, ve2, src, dst, W1, b3, out);
}

// round 4
// speedup vs baseline: 3.8665x; 3.8665x over previous
#include <cuda_runtime.h>
#include <math.h>
#include <stdint.h>

#define N_NODES 50000
#define N_EDGES 800000
#define HID     384
#define DOUT    128

// ---------------- device scratch (no cudaMalloc allowed) ----------------
__device__ float g_P[(size_t)N_NODES * HID];     // vc @ W1[0:128]
__device__ float g_Q[(size_t)N_NODES * HID];     // vc @ W1[128:256] + b1
__device__ float g_H[(size_t)N_EDGES * HID];     // hidden activations (1.23 GB)
__device__ float g_W23[HID * DOUT];              // W2[:,1:] @ W3
__device__ float g_w20[HID];                     // W2[:,0]
__device__ float g_c0[DOUT];                     // b2[1:] @ W3
__device__ float g_b20;                          // b2[0]

// ---------------- tf32 helpers ----------------
__device__ __forceinline__ uint32_t f2tf(float f) {
    uint32_t u; asm("cvt.rna.tf32.f32 %0, %1;" : "=r"(u) : "f"(f)); return u;
}
__device__ __forceinline__ void mma_tf32(float c[4],
        uint32_t a0, uint32_t a1, uint32_t a2, uint32_t a3,
        uint32_t b0, uint32_t b1) {
    asm volatile("mma.sync.aligned.m16n8k8.row.col.f32.tf32.tf32.f32 "
        "{%0,%1,%2,%3}, {%4,%5,%6,%7}, {%8,%9}, {%0,%1,%2,%3};"
        : "+f"(c[0]), "+f"(c[1]), "+f"(c[2]), "+f"(c[3])
        : "r"(a0), "r"(a1), "r"(a2), "r"(a3), "r"(b0), "r"(b1));
}

// ---------------- tiny precompute kernels ----------------
__global__ void k_w23(const float* __restrict__ W2, const float* __restrict__ W3) {
    __shared__ float s[512];
    int k = blockIdx.x;          // 0..383
    int t = threadIdx.x;         // 0..127
    for (int j = t; j < 512; j += 128) s[j] = W2[k * 513 + 1 + j];
    __syncthreads();
    float acc = 0.f;
#pragma unroll 8
    for (int j = 0; j < 512; j++) acc = fmaf(s[j], W3[j * DOUT + t], acc);
    g_W23[k * DOUT + t] = acc;
}

__global__ void k_misc(const float* __restrict__ W2, const float* __restrict__ b2,
                       const float* __restrict__ W3) {
    int t = threadIdx.x;  // 512 threads
    if (t < HID) g_w20[t] = W2[t * 513];
    if (t < DOUT) {
        float acc = 0.f;
        for (int j = 0; j < 512; j++) acc = fmaf(b2[1 + j], W3[j * DOUT + t], acc);
        g_c0[t] = acc;
    }
    if (t == 0) g_b20 = b2[0];
}

// ---------------- k_pq: P|Q node GEMM via tf32 mma ----------------
// grid (6, 1563), block 256. chunk = half*3 + nc; half 0->P, 1->Q(+b1).
#define PQ_TM 32
__global__ void __launch_bounds__(256) k_pq(const float* __restrict__ vc,
                                            const float* __restrict__ W1,
                                            const float* __restrict__ b1) {
    extern __shared__ uint32_t smu[];
    uint32_t* s_w = smu;               // [128][136]
    uint32_t* s_x = smu + 128 * 136;   // [32][132]
    int t = threadIdx.x;
    int chunk = blockIdx.x;
    int half = chunk / 3, nc = chunk - half * 3;
    int n0t = blockIdx.y * PQ_TM;

    for (int i = t; i < 128 * 128; i += 256) {
        int k = i >> 7, n = i & 127;
        s_w[k * 136 + n] = f2tf(W1[(size_t)(half * 128 + k) * HID + nc * 128 + n]);
    }
    for (int i = t; i < PQ_TM * 128; i += 256) {
        int r = i >> 7, k = i & 127;
        int node = n0t + r; if (node >= N_NODES) node = N_NODES - 1;
        s_x[r * 132 + k] = f2tf(vc[(size_t)node * 128 + k]);
    }
    __syncthreads();

    int warp = t >> 5, lane = t & 31;
    int wm = warp >> 2, wn = warp & 3;
    int g = lane >> 2, tt = lane & 3;
    int mb = wm * 16;

    float acc[4][4];
#pragma unroll
    for (int j = 0; j < 4; j++) {
        int col = nc * 128 + wn * 32 + j * 8 + 2 * tt;
        float bv0 = half ? b1[col] : 0.f;
        float bv1 = half ? b1[col + 1] : 0.f;
        acc[j][0] = bv0; acc[j][1] = bv1; acc[j][2] = bv0; acc[j][3] = bv1;
    }
#pragma unroll 4
    for (int ks = 0; ks < 16; ks++) {
        int k0 = ks * 8;
        uint32_t a0 = s_x[(mb + g) * 132 + k0 + tt];
        uint32_t a1 = s_x[(mb + g + 8) * 132 + k0 + tt];
        uint32_t a2 = s_x[(mb + g) * 132 + k0 + tt + 4];
        uint32_t a3 = s_x[(mb + g + 8) * 132 + k0 + tt + 4];
#pragma unroll
        for (int j = 0; j < 4; j++) {
            int n0 = wn * 32 + j * 8;
            uint32_t b0 = s_w[(k0 + tt) * 136 + n0 + g];
            uint32_t b1r = s_w[(k0 + tt + 4) * 136 + n0 + g];
            mma_tf32(acc[j], a0, a1, a2, a3, b0, b1r);
        }
    }
    float* dstp = half ? g_Q : g_P;
    int r_lo = n0t + mb + g, r_hi = r_lo + 8;
#pragma unroll
    for (int j = 0; j < 4; j++) {
        int col = nc * 128 + wn * 32 + j * 8 + 2 * tt;
        if (r_lo < N_NODES)
            *(float2*)&dstp[(size_t)r_lo * HID + col] = make_float2(acc[j][0], acc[j][1]);
        if (r_hi < N_NODES)
            *(float2*)&dstp[(size_t)r_hi * HID + col] = make_float2(acc[j][2], acc[j][3]);
    }
}

// ---------------- k_h: h = relu(P[src]+Q[dst] + ve@Wve) ----------------
// persistent, grid (3, 96), block 256. C-init = P/Q gather at frag coords.
#define A_TM 32
__global__ void __launch_bounds__(256) k_h(const float* __restrict__ ve1,
                                           const float* __restrict__ ve2,
                                           const int*   __restrict__ src,
                                           const int*   __restrict__ dst,
                                           const float* __restrict__ W1) {
    extern __shared__ uint32_t smu[];
    uint32_t* s_w = smu;                 // [128][136]
    uint32_t* s_x = smu + 128 * 136;     // [32][132]
    int* s_src = (int*)(s_x + 32 * 132);
    int* s_dst = s_src + 32;
    int t = threadIdx.x;
    int nc = blockIdx.x;

    for (int i = t; i < 128 * 128; i += 256) {
        int k = i >> 7, n = i & 127;
        s_w[k * 136 + n] = f2tf(W1[(size_t)(256 + k) * HID + nc * 128 + n]);
    }
    int warp = t >> 5, lane = t & 31;
    int wm = warp >> 2, wn = warp & 3;
    int g = lane >> 2, tt = lane & 3;
    int mb = wm * 16;

    for (int tile = blockIdx.y; tile < N_EDGES / A_TM; tile += gridDim.y) {
        int e0 = tile * A_TM;
        __syncthreads();   // previous iter readers done (also covers weight load)
        if (t < 32) s_src[t] = src[e0 + t];
        else if (t < 64) s_dst[t - 32] = dst[e0 + t - 32];
        for (int i = t; i < A_TM * 128; i += 256) {
            int r = i >> 7, k = i & 127;
            float v = (k < 64) ? ve1[(size_t)(e0 + r) * 64 + k]
                               : ve2[(size_t)(e0 + r) * 64 + k - 64];
            s_x[r * 132 + k] = f2tf(v);
        }
        __syncthreads();

        int rl = mb + g, rh = rl + 8;
        const float* Pl = g_P + (size_t)s_src[rl] * HID;
        const float* Ql = g_Q + (size_t)s_dst[rl] * HID;
        const float* Ph = g_P + (size_t)s_src[rh] * HID;
        const float* Qh = g_Q + (size_t)s_dst[rh] * HID;
        float acc[4][4];
#pragma unroll
        for (int j = 0; j < 4; j++) {
            int col = nc * 128 + wn * 32 + j * 8 + 2 * tt;
            float2 p  = *(const float2*)&Pl[col];
            float2 q  = *(const float2*)&Ql[col];
            float2 p2 = *(const float2*)&Ph[col];
            float2 q2 = *(const float2*)&Qh[col];
            acc[j][0] = p.x + q.x;   acc[j][1] = p.y + q.y;
            acc[j][2] = p2.x + q2.x; acc[j][3] = p2.y + q2.y;
        }
#pragma unroll 4
        for (int ks = 0; ks < 16; ks++) {
            int k0 = ks * 8;
            uint32_t a0 = s_x[(mb + g) * 132 + k0 + tt];
            uint32_t a1 = s_x[(mb + g + 8) * 132 + k0 + tt];
            uint32_t a2 = s_x[(mb + g) * 132 + k0 + tt + 4];
            uint32_t a3 = s_x[(mb + g + 8) * 132 + k0 + tt + 4];
#pragma unroll
            for (int j = 0; j < 4; j++) {
                int n0 = wn * 32 + j * 8;
                uint32_t b0 = s_w[(k0 + tt) * 136 + n0 + g];
                uint32_t b1r = s_w[(k0 + tt + 4) * 136 + n0 + g];
                mma_tf32(acc[j], a0, a1, a2, a3, b0, b1r);
            }
        }
#pragma unroll
        for (int j = 0; j < 4; j++) {
            int col = nc * 128 + wn * 32 + j * 8 + 2 * tt;
            *(float2*)&g_H[(size_t)(e0 + rl) * HID + col] =
                make_float2(fmaxf(acc[j][0], 0.f), fmaxf(acc[j][1], 0.f));
            *(float2*)&g_H[(size_t)(e0 + rh) * HID + col] =
                make_float2(fmaxf(acc[j][2], 0.f), fmaxf(acc[j][3], 0.f));
        }
    }
}

// ---------------- k_out: out = gate*(h@W23 + c0) + b3 ----------------
// persistent, grid 148, block 512 (16 warps). W23 column strip in registers.
#define B_TM 32
__global__ void __launch_bounds__(512, 1) k_out(const float* __restrict__ b3,
                                                float* __restrict__ out) {
    extern __shared__ float smf[];
    float* s_h    = smf;                 // [32][388] tf32-rounded floats
    float* s_w20  = s_h + B_TM * 388;    // 384
    float* s_c0   = s_w20 + HID;         // 128
    float* s_b3   = s_c0 + DOUT;         // 128
    float* s_gate = s_b3 + DOUT;         // 32
    int t = threadIdx.x;
    int warp = t >> 5, lane = t & 31;
    int g = lane >> 2, tt = lane & 3;

    if (t < HID) s_w20[t] = g_w20[t];
    else if (t < HID + DOUT) s_c0[t - HID] = g_c0[t - HID];
    if (t >= 256 && t < 256 + DOUT) s_b3[t - 256] = b3[t - 256];

    // W23 strip in registers: warp owns cols [n0, n0+8), full K=384
    int n0 = warp * 8;
    uint32_t breg[96];
#pragma unroll
    for (int kk = 0; kk < 48; kk++) {
        breg[2 * kk]     = f2tf(g_W23[(kk * 8 + tt) * DOUT + n0 + g]);
        breg[2 * kk + 1] = f2tf(g_W23[(kk * 8 + tt + 4) * DOUT + n0 + g]);
    }
    float b20 = g_b20;

    for (int tile = blockIdx.x; tile < N_EDGES / B_TM; tile += gridDim.x) {
        size_t e0 = (size_t)tile * B_TM;
        __syncthreads();
        for (int i = t; i < B_TM * HID; i += 512) {
            int r = i / HID, k = i - r * HID;
            s_h[r * 388 + k] = __uint_as_float(f2tf(g_H[e0 * HID + i]));
        }
        __syncthreads();
        // gate: 16 warps x 2 rows, lane-parallel dot + shfl reduce
#pragma unroll
        for (int rr = 0; rr < 2; rr++) {
            int row = warp + 16 * rr;
            float s = 0.f;
#pragma unroll
            for (int i = 0; i < 12; i++)
                s += s_h[row * 388 + lane + i * 32] * s_w20[lane + i * 32];
#pragma unroll
            for (int o = 16; o; o >>= 1) s += __shfl_xor_sync(0xffffffffu, s, o);
            if (lane == 0) s_gate[row] = 1.f / (1.f + expf(-(s + b20)));
        }
        __syncthreads();

        float acc[2][4];
#pragma unroll
        for (int m = 0; m < 2; m++)
#pragma unroll
            for (int i = 0; i < 4; i++) acc[m][i] = 0.f;
#pragma unroll
        for (int kk = 0; kk < 48; kk++) {
            int k0 = kk * 8;
#pragma unroll
            for (int m = 0; m < 2; m++) {
                int rb = m * 16;
                uint32_t a0 = __float_as_uint(s_h[(rb + g) * 388 + k0 + tt]);
                uint32_t a1 = __float_as_uint(s_h[(rb + g + 8) * 388 + k0 + tt]);
                uint32_t a2 = __float_as_uint(s_h[(rb + g) * 388 + k0 + tt + 4]);
                uint32_t a3 = __float_as_uint(s_h[(rb + g + 8) * 388 + k0 + tt + 4]);
                mma_tf32(acc[m], a0, a1, a2, a3, breg[2 * kk], breg[2 * kk + 1]);
            }
        }
        float c0x = s_c0[n0 + 2 * tt], c0y = s_c0[n0 + 2 * tt + 1];
        float b3x = s_b3[n0 + 2 * tt], b3y = s_b3[n0 + 2 * tt + 1];
#pragma unroll
        for (int m = 0; m < 2; m++) {
            int rl = m * 16 + g, rh = rl + 8;
            float kl = s_gate[rl], kh = s_gate[rh];
            float2 o0 = make_float2(fmaf(kl, acc[m][0] + c0x, b3x),
                                    fmaf(kl, acc[m][1] + c0y, b3y));
            float2 o1 = make_float2(fmaf(kh, acc[m][2] + c0x, b3x),
                                    fmaf(kh, acc[m][3] + c0y, b3y));
            *(float2*)&out[(e0 + rl) * DOUT + n0 + 2 * tt] = o0;
            *(float2*)&out[(e0 + rh) * DOUT + n0 + 2 * tt] = o1;
        }
    }
}

// ---------------- launch ----------------
extern "C" void kernel_launch(void* const* d_in, const int* in_sizes, int n_in,
                              void* d_out, int out_size) {
    const float* vc  = (const float*)d_in[0];
    const float* ve1 = (const float*)d_in[1];
    const float* ve2 = (const float*)d_in[2];
    const int*   src = (const int*)  d_in[3];
    const int*   dst = (const int*)  d_in[4];
    const float* W1  = (const float*)d_in[5];
    const float* b1  = (const float*)d_in[6];
    const float* W2  = (const float*)d_in[7];
    const float* b2  = (const float*)d_in[8];
    const float* W3  = (const float*)d_in[9];
    const float* b3  = (const float*)d_in[10];
    float* out = (float*)d_out;

    const int smem_pq  = (128 * 136 + 32 * 132) * 4;          // 86528
    const int smem_h   = smem_pq + 64 * 4;                    // + idx
    const int smem_out = (B_TM * 388 + HID + 2 * DOUT + B_TM) * 4;

    cudaFuncSetAttribute(k_pq,  cudaFuncAttributeMaxDynamicSharedMemorySize, smem_pq);
    cudaFuncSetAttribute(k_h,   cudaFuncAttributeMaxDynamicSharedMemorySize, smem_h);
    cudaFuncSetAttribute(k_out, cudaFuncAttributeMaxDynamicSharedMemorySize, smem_out);

    k_w23 <<<HID, 128>>>(W2, W3);
    k_misc<<<1, 512>>>(W2, b2, W3);
    k_pq  <<<dim3(6, (N_NODES + PQ_TM - 1) / PQ_TM), 256, smem_pq>>>(vc, W1, b1);
    k_h   <<<dim3(3, 96), 256, smem_h>>>(ve1, ve2, src, dst, W1);
    k_out <<<148, 512, smem_out>>>(b3, out);
}

// round 5
// speedup vs baseline: 8.3670x; 2.1640x over previous
#include <cuda_runtime.h>
#include <cuda_fp16.h>
#include <math.h>
#include <stdint.h>

#define N_NODES 50000
#define N_EDGES 800000
#define HID     384
#define DOUT    128
#define TM      64                  // edges per tile
#define NTILES  (N_EDGES / TM)      // 12500

// ---------------- device scratch ----------------
__device__ __half g_P16[(size_t)N_NODES * HID];   // vc @ W1[0:128]        (fp16)
__device__ __half g_Q16[(size_t)N_NODES * HID];   // vc @ W1[128:256] + b1 (fp16)
__device__ float  g_W23[HID * DOUT];              // W2[:,1:] @ W3
__device__ float  g_w20[HID];                     // W2[:,0]
__device__ float  g_c0[DOUT];                     // b2[1:] @ W3
__device__ float  g_b20;                          // b2[0]

// ---------------- helpers ----------------
__device__ __forceinline__ uint32_t f2tf(float f) {
    uint32_t u; asm("cvt.rna.tf32.f32 %0, %1;" : "=r"(u) : "f"(f)); return u;
}
__device__ __forceinline__ void mma_tf32(float c[4],
        uint32_t a0, uint32_t a1, uint32_t a2, uint32_t a3,
        uint32_t b0, uint32_t b1) {
    asm volatile("mma.sync.aligned.m16n8k8.row.col.f32.tf32.tf32.f32 "
        "{%0,%1,%2,%3}, {%4,%5,%6,%7}, {%8,%9}, {%0,%1,%2,%3};"
        : "+f"(c[0]), "+f"(c[1]), "+f"(c[2]), "+f"(c[3])
        : "r"(a0), "r"(a1), "r"(a2), "r"(a3), "r"(b0), "r"(b1));
}
__device__ __forceinline__ void mma_f16(float c[4],
        uint32_t a0, uint32_t a1, uint32_t a2, uint32_t a3,
        uint32_t b0, uint32_t b1) {
    asm volatile("mma.sync.aligned.m16n8k16.row.col.f32.f16.f16.f32 "
        "{%0,%1,%2,%3}, {%4,%5,%6,%7}, {%8,%9}, {%0,%1,%2,%3};"
        : "+f"(c[0]), "+f"(c[1]), "+f"(c[2]), "+f"(c[3])
        : "r"(a0), "r"(a1), "r"(a2), "r"(a3), "r"(b0), "r"(b1));
}
__device__ __forceinline__ uint32_t f22h2u(float a, float b) {
    __half2 h = __floats2half2_rn(a, b);
    return *reinterpret_cast<uint32_t*>(&h);
}
__device__ __forceinline__ float2 u2f2(uint32_t u) {
    __half2 h = *reinterpret_cast<__half2*>(&u);
    return __half22float2(h);
}

// ---------------- tiny precompute kernels ----------------
__global__ void k_w23(const float* __restrict__ W2, const float* __restrict__ W3) {
    __shared__ float s[512];
    int k = blockIdx.x;          // 0..383
    int t = threadIdx.x;         // 0..127
    for (int j = t; j < 512; j += 128) s[j] = W2[k * 513 + 1 + j];
    __syncthreads();
    float acc = 0.f;
#pragma unroll 8
    for (int j = 0; j < 512; j++) acc = fmaf(s[j], W3[j * DOUT + t], acc);
    g_W23[k * DOUT + t] = acc;
}

__global__ void k_misc(const float* __restrict__ W2, const float* __restrict__ b2,
                       const float* __restrict__ W3) {
    int t = threadIdx.x;  // 512 threads
    if (t < HID) g_w20[t] = W2[t * 513];
    if (t < DOUT) {
        float acc = 0.f;
        for (int j = 0; j < 512; j++) acc = fmaf(b2[1 + j], W3[j * DOUT + t], acc);
        g_c0[t] = acc;
    }
    if (t == 0) g_b20 = b2[0];
}

// ---------------- k_pq: P|Q node GEMM (tf32 mma), fp16 output ----------------
#define PQ_TM 32
__global__ void __launch_bounds__(256) k_pq(const float* __restrict__ vc,
                                            const float* __restrict__ W1,
                                            const float* __restrict__ b1) {
    extern __shared__ uint32_t smu[];
    uint32_t* s_w = smu;               // [128][136]
    uint32_t* s_x = smu + 128 * 136;   // [32][132]
    int t = threadIdx.x;
    int chunk = blockIdx.x;
    int half = chunk / 3, nc = chunk - half * 3;
    int n0t = blockIdx.y * PQ_TM;

    for (int i = t; i < 128 * 128; i += 256) {
        int k = i >> 7, n = i & 127;
        s_w[k * 136 + n] = f2tf(W1[(size_t)(half * 128 + k) * HID + nc * 128 + n]);
    }
    for (int i = t; i < PQ_TM * 128; i += 256) {
        int r = i >> 7, k = i & 127;
        int node = n0t + r; if (node >= N_NODES) node = N_NODES - 1;
        s_x[r * 132 + k] = f2tf(vc[(size_t)node * 128 + k]);
    }
    __syncthreads();

    int warp = t >> 5, lane = t & 31;
    int wm = warp >> 2, wn = warp & 3;
    int g = lane >> 2, tt = lane & 3;
    int mb = wm * 16;

    float acc[4][4];
#pragma unroll
    for (int j = 0; j < 4; j++) {
        int col = nc * 128 + wn * 32 + j * 8 + 2 * tt;
        float bv0 = half ? b1[col] : 0.f;
        float bv1 = half ? b1[col + 1] : 0.f;
        acc[j][0] = bv0; acc[j][1] = bv1; acc[j][2] = bv0; acc[j][3] = bv1;
    }
#pragma unroll 4
    for (int ks = 0; ks < 16; ks++) {
        int k0 = ks * 8;
        uint32_t a0 = s_x[(mb + g) * 132 + k0 + tt];
        uint32_t a1 = s_x[(mb + g + 8) * 132 + k0 + tt];
        uint32_t a2 = s_x[(mb + g) * 132 + k0 + tt + 4];
        uint32_t a3 = s_x[(mb + g + 8) * 132 + k0 + tt + 4];
#pragma unroll
        for (int j = 0; j < 4; j++) {
            int n0 = wn * 32 + j * 8;
            uint32_t b0 = s_w[(k0 + tt) * 136 + n0 + g];
            uint32_t b1r = s_w[(k0 + tt + 4) * 136 + n0 + g];
            mma_tf32(acc[j], a0, a1, a2, a3, b0, b1r);
        }
    }
    __half* dstp = half ? g_Q16 : g_P16;
    int r_lo = n0t + mb + g, r_hi = r_lo + 8;
#pragma unroll
    for (int j = 0; j < 4; j++) {
        int col = nc * 128 + wn * 32 + j * 8 + 2 * tt;
        if (r_lo < N_NODES)
            *(uint32_t*)&dstp[(size_t)r_lo * HID + col] = f22h2u(acc[j][0], acc[j][1]);
        if (r_hi < N_NODES)
            *(uint32_t*)&dstp[(size_t)r_hi * HID + col] = f22h2u(acc[j][2], acc[j][3]);
    }
}

// ---------------- k_fused: edge pipeline, fully fused, fp16 mma ----------------
// h = relu(P[src]+Q[dst]+ve@Wve) chunked over 3 n-chunks of 128;
// y += h_chunk @ W23[k-chunk]; gate accumulates; out = sig(gate)*(y+c0)+b3.
// smem: Wve[n][k] 384x64w, W23[n][k] 128x192w, x 64x64w, h 64x64w  (XOR swizzle)
__global__ void __launch_bounds__(256, 1) k_fused(
    const float* __restrict__ ve1, const float* __restrict__ ve2,
    const int*   __restrict__ src, const int* __restrict__ dst,
    const float* __restrict__ W1,  const float* __restrict__ b3,
    float* __restrict__ out)
{
    extern __shared__ uint32_t sm[];
    uint32_t* s_wve = sm;                       // 384*64 words
    uint32_t* s_w23 = s_wve + 384 * 64;         // 128*192 words
    uint32_t* s_x   = s_w23 + 128 * 192;        // 64*64
    uint32_t* s_h   = s_x + 64 * 64;            // 64*64
    float*    s_gate = (float*)(s_h + 64 * 64); // 64
    int*      s_src  = (int*)(s_gate + 64);     // 64
    int*      s_dst  = s_src + 64;              // 64

    int t = threadIdx.x;
    int warp = t >> 5, lane = t & 31;
    int wm = warp >> 2, wn = warp & 3;          // 2 x 4 warp grid
    int g = lane >> 2, tt = lane & 3;
    uint32_t gsw = (uint32_t)g << 2;

    // ---- load weights into smem (once) ----
    for (int i = t; i < 384 * 64; i += 256) {       // Wve[n][k] = W1[256+k][n]
        int n = i >> 6, w = i & 63;
        int k = 2 * w;
        s_wve[(n << 6) + (w ^ ((n & 7) << 2))] =
            f22h2u(W1[(size_t)(256 + k) * HID + n], W1[(size_t)(256 + k + 1) * HID + n]);
    }
    for (int i = t; i < 128 * 192; i += 256) {      // W23s[n][k] = g_W23[k][n]
        int n = i / 192, w = i - n * 192;
        int k = 2 * w;
        s_w23[n * 192 + (w ^ ((n & 7) << 2))] =
            f22h2u(g_W23[k * DOUT + n], g_W23[(k + 1) * DOUT + n]);
    }
    // per-thread epilogue constants
    float2 c0r[4], b3r[4];
#pragma unroll
    for (int j = 0; j < 4; j++) {
        int col = wn * 32 + j * 8 + 2 * tt;
        c0r[j] = *(const float2*)&g_c0[col];
        b3r[j] = *(const float2*)&b3[col];
    }
    float b20 = g_b20;
    int grow = warp * 8 + g;                        // gate row owned by this quad

    for (int tile = blockIdx.x; tile < NTILES; tile += gridDim.x) {
        int e0 = tile * TM;
        // ---- stage edge features + indices ----
        if (t < 64) s_src[t] = src[e0 + t];
        else if (t < 128) s_dst[t - 64] = dst[e0 + t - 64];
        for (int i = t; i < 64 * 64; i += 256) {
            int r = i >> 6, w = i & 63;
            float2 v;
            if (w < 32) v = *(const float2*)&ve1[(size_t)(e0 + r) * 64 + 2 * w];
            else        v = *(const float2*)&ve2[(size_t)(e0 + r) * 64 + 2 * w - 64];
            s_x[(r << 6) + (w ^ ((r & 7) << 2))] = f22h2u(v.x, v.y);
        }
        __syncthreads();

        float acc2[2][4][4];
#pragma unroll
        for (int mf = 0; mf < 2; mf++)
#pragma unroll
            for (int j = 0; j < 4; j++)
#pragma unroll
                for (int i = 0; i < 4; i++) acc2[mf][j][i] = 0.f;
        float gacc = 0.f;

#pragma unroll 1
        for (int c = 0; c < 3; c++) {
            // ---- prefetch P/Q fragments for this chunk (hidden under mma) ----
            uint32_t pq[4][4][2];
#pragma unroll
            for (int rr = 0; rr < 4; rr++) {
                int r = wm * 32 + (rr >> 1) * 16 + (rr & 1) * 8 + g;
                const __half* Pp = g_P16 + (size_t)s_src[r] * HID + 128 * c;
                const __half* Qp = g_Q16 + (size_t)s_dst[r] * HID + 128 * c;
#pragma unroll
                for (int j = 0; j < 4; j++) {
                    int cc = wn * 32 + j * 8 + 2 * tt;
                    pq[rr][j][0] = *(const uint32_t*)(Pp + cc);
                    pq[rr][j][1] = *(const uint32_t*)(Qp + cc);
                }
            }
            // ---- GEMM1 chunk: xW (64 x 128 of h) ----
            float acc1[2][4][4];
#pragma unroll
            for (int mf = 0; mf < 2; mf++)
#pragma unroll
                for (int j = 0; j < 4; j++)
#pragma unroll
                    for (int i = 0; i < 4; i++) acc1[mf][j][i] = 0.f;
#pragma unroll
            for (int ks = 0; ks < 8; ks++) {
                uint32_t a[2][4];
#pragma unroll
                for (int mf = 0; mf < 2; mf++) {
                    int ra = wm * 32 + mf * 16 + g, rb = ra + 8;
                    int wa = 8 * ks + tt, wb = wa + 4;
                    a[mf][0] = s_x[(ra << 6) + (wa ^ gsw)];
                    a[mf][1] = s_x[(rb << 6) + (wa ^ gsw)];
                    a[mf][2] = s_x[(ra << 6) + (wb ^ gsw)];
                    a[mf][3] = s_x[(rb << 6) + (wb ^ gsw)];
                }
#pragma unroll
                for (int j = 0; j < 4; j++) {
                    int n = 128 * c + wn * 32 + j * 8 + g;
                    uint32_t b0 = s_wve[(n << 6) + ((8 * ks + tt) ^ gsw)];
                    uint32_t b1 = s_wve[(n << 6) + ((8 * ks + 4 + tt) ^ gsw)];
                    mma_f16(acc1[0][j], a[0][0], a[0][1], a[0][2], a[0][3], b0, b1);
                    mma_f16(acc1[1][j], a[1][0], a[1][1], a[1][2], a[1][3], b0, b1);
                }
            }
            // ---- epilogue: + P + Q, relu, store h chunk ----
#pragma unroll
            for (int mf = 0; mf < 2; mf++)
#pragma unroll
                for (int j = 0; j < 4; j++) {
                    int wcl = wn * 16 + j * 4 + tt;
                    int rl = wm * 32 + mf * 16 + g, rh = rl + 8;
                    float2 pl = u2f2(pq[2 * mf][j][0]), ql = u2f2(pq[2 * mf][j][1]);
                    float2 ph = u2f2(pq[2 * mf + 1][j][0]), qh = u2f2(pq[2 * mf + 1][j][1]);
                    float h0 = fmaxf(acc1[mf][j][0] + pl.x + ql.x, 0.f);
                    float h1 = fmaxf(acc1[mf][j][1] + pl.y + ql.y, 0.f);
                    float h2 = fmaxf(acc1[mf][j][2] + ph.x + qh.x, 0.f);
                    float h3 = fmaxf(acc1[mf][j][3] + ph.y + qh.y, 0.f);
                    s_h[(rl << 6) + (wcl ^ gsw)] = f22h2u(h0, h1);
                    s_h[(rh << 6) + (wcl ^ gsw)] = f22h2u(h2, h3);
                }
            __syncthreads();   // h chunk visible

            // ---- gate partial ----
#pragma unroll
            for (int i = 0; i < 16; i++) {
                int w = 4 * i + tt;
                float2 hv = u2f2(s_h[(grow << 6) + (w ^ ((grow & 7) << 2))]);
                float2 wv = *(const float2*)&g_w20[128 * c + 2 * w];
                gacc = fmaf(hv.x, wv.x, fmaf(hv.y, wv.y, gacc));
            }
            // ---- GEMM2 partial: acc2 += h_chunk @ W23[kchunk] ----
#pragma unroll
            for (int ks = 0; ks < 8; ks++) {
                uint32_t a[2][4];
#pragma unroll
                for (int mf = 0; mf < 2; mf++) {
                    int ra = wm * 32 + mf * 16 + g, rb = ra + 8;
                    int wa = 8 * ks + tt, wb = wa + 4;
                    a[mf][0] = s_h[(ra << 6) + (wa ^ gsw)];
                    a[mf][1] = s_h[(rb << 6) + (wa ^ gsw)];
                    a[mf][2] = s_h[(ra << 6) + (wb ^ gsw)];
                    a[mf][3] = s_h[(rb << 6) + (wb ^ gsw)];
                }
#pragma unroll
                for (int j = 0; j < 4; j++) {
                    int n = wn * 32 + j * 8 + g;
                    int w0 = 64 * c + 8 * ks + tt;
                    uint32_t b0 = s_w23[n * 192 + (w0 ^ gsw)];
                    uint32_t b1 = s_w23[n * 192 + ((w0 + 4) ^ gsw)];
                    mma_f16(acc2[0][j], a[0][0], a[0][1], a[0][2], a[0][3], b0, b1);
                    mma_f16(acc2[1][j], a[1][0], a[1][1], a[1][2], a[1][3], b0, b1);
                }
            }
            __syncthreads();   // before h chunk overwrite / s_x refill
        }
        // ---- gate finalize ----
        gacc += __shfl_xor_sync(0xffffffffu, gacc, 1);
        gacc += __shfl_xor_sync(0xffffffffu, gacc, 2);
        if (tt == 0) s_gate[grow] = 1.f / (1.f + expf(-(gacc + b20)));
        __syncthreads();
        // ---- output epilogue ----
#pragma unroll
        for (int mf = 0; mf < 2; mf++)
#pragma unroll
            for (int j = 0; j < 4; j++) {
                int rl = wm * 32 + mf * 16 + g, rh = rl + 8;
                int col = wn * 32 + j * 8 + 2 * tt;
                float kl = s_gate[rl], kh = s_gate[rh];
                float2 o0, o1;
                o0.x = fmaf(kl, acc2[mf][j][0] + c0r[j].x, b3r[j].x);
                o0.y = fmaf(kl, acc2[mf][j][1] + c0r[j].y, b3r[j].y);
                o1.x = fmaf(kh, acc2[mf][j][2] + c0r[j].x, b3r[j].x);
                o1.y = fmaf(kh, acc2[mf][j][3] + c0r[j].y, b3r[j].y);
                *(float2*)&out[(size_t)(e0 + rl) * DOUT + col] = o0;
                *(float2*)&out[(size_t)(e0 + rh) * DOUT + col] = o1;
            }
    }
}

// ---------------- launch ----------------
extern "C" void kernel_launch(void* const* d_in, const int* in_sizes, int n_in,
                              void* d_out, int out_size) {
    const float* vc  = (const float*)d_in[0];
    const float* ve1 = (const float*)d_in[1];
    const float* ve2 = (const float*)d_in[2];
    const int*   src = (const int*)  d_in[3];
    const int*   dst = (const int*)  d_in[4];
    const float* W1  = (const float*)d_in[5];
    const float* b1  = (const float*)d_in[6];
    const float* W2  = (const float*)d_in[7];
    const float* b2  = (const float*)d_in[8];
    const float* W3  = (const float*)d_in[9];
    const float* b3  = (const float*)d_in[10];
    float* out = (float*)d_out;

    const int smem_pq = (128 * 136 + 32 * 132) * 4;                        // 86528
    const int smem_f  = (384 * 64 + 128 * 192 + 64 * 64 + 64 * 64) * 4
                        + 64 * 4 + 64 * 4 + 64 * 4;                        // 230144

    cudaFuncSetAttribute(k_pq,    cudaFuncAttributeMaxDynamicSharedMemorySize, smem_pq);
    cudaFuncSetAttribute(k_fused, cudaFuncAttributeMaxDynamicSharedMemorySize, smem_f);

    k_w23 <<<HID, 128>>>(W2, W3);
    k_misc<<<1, 512>>>(W2, b2, W3);
    k_pq  <<<dim3(6, (N_NODES + PQ_TM - 1) / PQ_TM), 256, smem_pq>>>(vc, W1, b1);
    k_fused<<<152, 256, smem_f>>>(ve1, ve2, src, dst, W1, b3, out);
}